// round 8
// baseline (speedup 1.0000x reference)
#include <cuda_runtime.h>
#include <cuda_bf16.h>
#include <math.h>

// Problem dims
#define BB 16
#define SS 100
#define LL 100          // MAX_CODE_LEN
#define FEAT 20         // INPUT_DIM
#define EMB 100
#define DD 320          // D = 20 + 3*100
#define RNNIN 340       // 2*20 + 3*100
#define HID 128
#define G4 512
#define NOUT 10

#define NVOC_N 10002
#define NVOC_P 50002
#define PROJ_NODE_BLOCKS 79   // ceil(10002/128)
#define PROJ_PATH_BLOCKS 391  // ceil(50002/128)
#define WS_STRIDE 68          // multiple of 4: float4 stays 16B-aligned
#define AS_STRIDE 104         // multiple of 4

// -------- scratch (device globals; no allocation allowed) --------
static __device__ float g_Tn[NVOC_N * 640];    // [v][0:320]=start proj, [v][320:640]=end proj
static __device__ float g_Tp[NVOC_P * 320];    // path proj
static __device__ float g_cw[BB*LL*SS];        // [b][l][s]
static __device__ float g_aw[BB*SS*LL];        // [b][s][l]
static __device__ float g_rnn[BB*SS*RNNIN];    // [b][s][340]
static __device__ float g_gx[BB*SS*G4];        // x-part gates
static __device__ float g_hs[BB*SS*HID];       // lstm outputs

__device__ __forceinline__ float sigf(float x) { return 1.0f / (1.0f + expf(-x)); }
__device__ __forceinline__ float tanh_fast(float x) {
    float y;
    asm("tanh.approx.f32 %0, %1;" : "=f"(y) : "f"(x));
    return y;
}

// dummy: aligns ncu's position-4 capture onto k1b_cw
__global__ void kdummy() {}

// ----------------------------------------------------------------
// KP: project embedding tables through W_trans column blocks.
// ----------------------------------------------------------------
__global__ void __launch_bounds__(256, 1)
kp_project(const float* __restrict__ etab_n,
           const float* __restrict__ etab_p,
           const float* __restrict__ Wt)
{
    extern __shared__ float sm[];
    float* A_s = sm;                        // 128 * 104
    float* W_s = sm + 128 * AS_STRIDE;      // 100 * 68

    const int t = threadIdx.x;
    const bool isnode = blockIdx.x < PROJ_NODE_BLOCKS;
    const int vb = isnode ? blockIdx.x : blockIdx.x - PROJ_NODE_BLOCKS;
    const int v0 = vb * 128;
    const int nv = isnode ? NVOC_N : NVOC_P;
    const float* tab = isnode ? etab_n : etab_p;
    float* outp = isnode ? g_Tn : g_Tp;
    const int ostride = isnode ? 640 : 320;
    const int ndb = isnode ? 10 : 5;

    for (int e = t; e < 128 * EMB; e += 256) {
        int r = e / EMB, k = e % EMB;
        float v = 0.f;
        if (v0 + r < nv) v = tab[(v0 + r) * EMB + k];
        A_s[r * AS_STRIDE + k] = v;
    }

    const int tx = t & 15;
    const int ty = t >> 4;
    const int d0 = tx * 4;
    const int r0 = ty * 8;

    for (int db = 0; db < ndb; db++) {
        const int dbase = db * 64;
        int wrow, kofs;
        if (isnode) {
            if (db < 5) { wrow = dbase;       kofs = 0;   }
            else        { wrow = dbase - 320; kofs = 100; }
        } else          { wrow = dbase;       kofs = 200; }

        __syncthreads();
        for (int e = t; e < 64 * EMB; e += 256) {
            int d = e / EMB, k = e % EMB;
            W_s[k * WS_STRIDE + d] = Wt[(wrow + d) * DD + kofs + k];
        }
        __syncthreads();

        float acc[8][4];
#pragma unroll
        for (int i = 0; i < 8; i++)
#pragma unroll
            for (int j = 0; j < 4; j++) acc[i][j] = 0.f;

#pragma unroll 2
        for (int k = 0; k < EMB; k += 4) {
            float4 wv0 = *(const float4*)&W_s[(k + 0) * WS_STRIDE + d0];
            float4 wv1 = *(const float4*)&W_s[(k + 1) * WS_STRIDE + d0];
            float4 wv2 = *(const float4*)&W_s[(k + 2) * WS_STRIDE + d0];
            float4 wv3 = *(const float4*)&W_s[(k + 3) * WS_STRIDE + d0];
#pragma unroll
            for (int i = 0; i < 8; i++) {
                float4 a = *(const float4*)&A_s[(r0 + i) * AS_STRIDE + k];
                acc[i][0] += a.x * wv0.x + a.y * wv1.x + a.z * wv2.x + a.w * wv3.x;
                acc[i][1] += a.x * wv0.y + a.y * wv1.y + a.z * wv2.y + a.w * wv3.y;
                acc[i][2] += a.x * wv0.z + a.y * wv1.z + a.z * wv2.z + a.w * wv3.z;
                acc[i][3] += a.x * wv0.w + a.y * wv1.w + a.z * wv2.w + a.w * wv3.w;
            }
        }
#pragma unroll
        for (int i = 0; i < 8; i++) {
            int r = v0 + r0 + i;
            if (r < nv) {
                float4 o = make_float4(acc[i][0], acc[i][1], acc[i][2], acc[i][3]);
                *(float4*)&outp[r * ostride + dbase + d0] = o;
            }
        }
    }
}

// ----------------------------------------------------------------
// K1b: per (b,s): f_proj = feat @ Wt4^T + bt; per context l:
//   cw = ba + sum_d Wa[d]*tanh(Tn_s[si][d]+Tn_e[ei][d]+Tp[pi][d]+fproj[d])
// ----------------------------------------------------------------
__global__ void __launch_bounds__(256, 4)
k1b_cw(const float* __restrict__ x,
       const float* __restrict__ Wt,
       const float* __restrict__ bt,
       const float* __restrict__ Wa,
       const float* __restrict__ ba)
{
    __shared__ int si[LL], pi[LL], ei[LL];
    __shared__ float4 fproj4[DD/4], was4[DD/4];
    __shared__ float feat_s[FEAT];
    float* fproj = (float*)fproj4;
    float* was   = (float*)was4;

    const int bs = blockIdx.x;
    const int b = bs / SS, s = bs % SS;
    const int t = threadIdx.x;

    if (t < LL) {
        int xb = bs * DD + FEAT + 3 * t;
        si[t] = (int)x[xb];
        pi[t] = (int)x[xb + 1];
        ei[t] = (int)x[xb + 2];
    }
    if (t < FEAT) feat_s[t] = x[bs * DD + t];
    __syncthreads();

    for (int d = t; d < DD; d += 256) {
        float acc = bt[d];
        const float* wrow = &Wt[d * DD + 300];
#pragma unroll
        for (int k = 0; k < FEAT; k++) acc += feat_s[k] * wrow[k];
        fproj[d] = acc;
        was[d] = Wa[d];
    }
    __syncthreads();

    const int warp = t >> 5, lane = t & 31;
    const float bav = ba[0];
    for (int l = warp; l < LL; l += 8) {
        const float4* pn = (const float4*)&g_Tn[si[l] * 640];
        const float4* pe = (const float4*)&g_Tn[ei[l] * 640 + 320];
        const float4* pp = (const float4*)&g_Tp[pi[l] * 320];
        float sum = 0.f;
        for (int j = lane; j < DD/4; j += 32) {
            float4 a = pn[j], bb4 = pe[j], cc = pp[j], f = fproj4[j], w = was4[j];
            sum += w.x * tanh_fast(a.x + bb4.x + cc.x + f.x)
                 + w.y * tanh_fast(a.y + bb4.y + cc.y + f.y)
                 + w.z * tanh_fast(a.z + bb4.z + cc.z + f.z)
                 + w.w * tanh_fast(a.w + bb4.w + cc.w + f.w);
        }
#pragma unroll
        for (int off = 16; off; off >>= 1) sum += __shfl_xor_sync(~0u, sum, off);
        if (lane == 0)
            g_cw[(b * LL + l) * SS + s] = sum + bav;
    }
}

// ----------------------------------------------------------------
// K2: softmax over s (axis=1) for each (b,l); write aw in [b][s][l]
// ----------------------------------------------------------------
__global__ void k2_softmax() {
    const int bl = blockIdx.x;
    const int t  = threadIdx.x;    // 128
    const float* row = g_cw + bl * SS;
    float v0 = (t < SS) ? row[t] : -3.0e38f;

    __shared__ float sw[4];
    float v = v0;
#pragma unroll
    for (int off = 16; off; off >>= 1) v = fmaxf(v, __shfl_xor_sync(~0u, v, off));
    if ((t & 31) == 0) sw[t >> 5] = v;
    __syncthreads();
    float mx = fmaxf(fmaxf(sw[0], sw[1]), fmaxf(sw[2], sw[3]));
    __syncthreads();

    float e = (t < SS) ? expf(v0 - mx) : 0.f;
    float sv = e;
#pragma unroll
    for (int off = 16; off; off >>= 1) sv += __shfl_xor_sync(~0u, sv, off);
    if ((t & 31) == 0) sw[t >> 5] = sv;
    __syncthreads();
    float tot = sw[0] + sw[1] + sw[2] + sw[3];

    if (t < SS) {
        int b = bl / LL, l = bl % LL;
        g_aw[(b * SS + t) * LL + l] = e / tot;
    }
}

// ----------------------------------------------------------------
// K3: code_vec via re-gather; rnn_in = [feat(20), code_vec(320)]
// ----------------------------------------------------------------
__global__ void k3_codevec(const float* __restrict__ x,
                           const float* __restrict__ etab_n,
                           const float* __restrict__ etab_p)
{
    __shared__ float aw_s[LL];
    __shared__ int si[LL], pi[LL], ei[LL];
    __shared__ float awsum_s;
    const int bs = blockIdx.x;
    const int t  = threadIdx.x;   // 128

    if (t < LL) {
        aw_s[t] = g_aw[bs * LL + t];
        int xb = bs * DD + FEAT + 3 * t;
        si[t] = (int)x[xb];
        pi[t] = (int)x[xb + 1];
        ei[t] = (int)x[xb + 2];
    }
    __syncthreads();
    if (t == 0) {
        float a = 0.f;
        for (int l = 0; l < LL; l++) a += aw_s[l];
        awsum_s = a;
    }
    __syncthreads();

    float* outrow = g_rnn + bs * RNNIN;
    for (int j = t; j < RNNIN; j += 128) {
        float v;
        if (j < FEAT) {
            v = x[bs * DD + j];
        } else {
            int k = j - FEAT;
            float acc = 0.f;
            if (k < EMB) {
                for (int l = 0; l < LL; l++) acc += etab_n[si[l] * EMB + k] * aw_s[l];
            } else if (k < 2 * EMB) {
                int km = k - EMB;
                for (int l = 0; l < LL; l++) acc += etab_n[ei[l] * EMB + km] * aw_s[l];
            } else if (k < 3 * EMB) {
                int km = k - 2 * EMB;
                for (int l = 0; l < LL; l++) acc += etab_p[pi[l] * EMB + km] * aw_s[l];
            } else {
                acc = x[bs * DD + (k - 3 * EMB)] * awsum_s;
            }
            v = acc;
        }
        outrow[j] = v;
    }
}

// ----------------------------------------------------------------
// K4: g_gx = rnn_in @ W_ih^T + b_ih + b_hh
// W_ih read in native [n][k] layout via float4 rows (no transpose).
// ----------------------------------------------------------------
__global__ void __launch_bounds__(512)
k4_gates(const float* __restrict__ Wih,
         const float* __restrict__ bih, const float* __restrict__ bhh)
{
    __shared__ float4 A_s4[16 * (RNNIN/4)];   // 16 rows x 85 float4
    float* A_s = (float*)A_s4;
    const int n  = threadIdx.x;
    const int r0 = blockIdx.x * 16;

    {   // float4 tile copy (16*340 floats, both sides 16B-aligned)
        const float4* src = (const float4*)&g_rnn[r0 * RNNIN];
        for (int e = n; e < 16 * (RNNIN/4); e += 512)
            A_s4[e] = src[e];
    }
    __syncthreads();

    const float4* wrow = (const float4*)&Wih[n * RNNIN];  // row n, 85 float4
    float acc[16];
#pragma unroll
    for (int i = 0; i < 16; i++) acc[i] = 0.f;

#pragma unroll 5
    for (int kk = 0; kk < RNNIN/4; kk++) {
        float4 w = wrow[kk];
#pragma unroll
        for (int i = 0; i < 16; i++) {
            float4 a = A_s4[i * (RNNIN/4) + kk];
            acc[i] += a.x * w.x + a.y * w.y + a.z * w.z + a.w * w.w;
        }
    }
    float bias = bih[n] + bhh[n];
#pragma unroll
    for (int i = 0; i < 16; i++)
        g_gx[(r0 + i) * G4 + n] = acc[i] + bias;
}

// ----------------------------------------------------------------
// K5: LSTM recurrence. One CTA per batch, 512 threads.
// W_hh read in native [n][k] layout via float4 rows: 32 LDG.128
// per thread per step instead of 128 scalar LDG (LSU-issue fix).
// ----------------------------------------------------------------
__global__ void __launch_bounds__(512)
k5_lstm(const float* __restrict__ Whh)
{
    __shared__ float4 h_s4[HID/4];
    __shared__ float gs[G4];
    float* h_s = (float*)h_s4;
    const int b = blockIdx.x;
    const int n = threadIdx.x;

    const float4* wrow = (const float4*)&Whh[n * HID];   // row n, 32 float4

    if (n < HID) h_s[n] = 0.f;
    float c = 0.f;
    __syncthreads();

    for (int s = 0; s < SS; s++) {
        float acc = g_gx[(b * SS + s) * G4 + n];
#pragma unroll 8
        for (int kk = 0; kk < HID/4; kk++) {
            float4 w  = wrow[kk];
            float4 h4 = h_s4[kk];
            acc += w.x * h4.x + w.y * h4.y + w.z * h4.z + w.w * h4.w;
        }
        gs[n] = acc;
        __syncthreads();
        if (n < HID) {
            float gi = gs[n];
            float gf = gs[HID + n];
            float gg = gs[2 * HID + n];
            float go = gs[3 * HID + n];
            c = sigf(gf) * c + sigf(gi) * tanhf(gg);
            float h = sigf(go) * tanhf(c);
            h_s[n] = h;
            g_hs[(b * SS + s) * HID + n] = h;
        }
        __syncthreads();
    }
}

// ----------------------------------------------------------------
// K6: out = sigmoid(hs @ W_fc^T + b_fc)
// ----------------------------------------------------------------
__global__ void k6_fc(const float* __restrict__ Wfc,
                      const float* __restrict__ bfc,
                      float* __restrict__ out)
{
    int t = blockIdx.x * blockDim.x + threadIdx.x;
    if (t >= BB * SS * NOUT) return;
    int bs = t / NOUT;
    int o  = t % NOUT;
    const float* hrow = g_hs + bs * HID;
    const float* wrow = Wfc + o * HID;
    float acc = bfc[o];
#pragma unroll 8
    for (int u = 0; u < HID; u++) acc += hrow[u] * wrow[u];
    out[t] = sigf(acc);
}

// ----------------------------------------------------------------
extern "C" void kernel_launch(void* const* d_in, const int* in_sizes, int n_in,
                              void* d_out, int out_size)
{
    const float* x      = (const float*)d_in[0];
    const float* etab_n = (const float*)d_in[1];
    const float* etab_p = (const float*)d_in[2];
    const float* Wt     = (const float*)d_in[3];
    const float* bt     = (const float*)d_in[4];
    const float* Wa     = (const float*)d_in[5];
    const float* ba     = (const float*)d_in[6];
    const float* Wih    = (const float*)d_in[7];
    const float* Whh    = (const float*)d_in[8];
    const float* bih    = (const float*)d_in[9];
    const float* bhh    = (const float*)d_in[10];
    const float* Wfc    = (const float*)d_in[11];
    const float* bfc    = (const float*)d_in[12];
    float* out = (float*)d_out;

    const int kp_smem = (128 * AS_STRIDE + 100 * WS_STRIDE) * 4;
    cudaFuncSetAttribute(kp_project, cudaFuncAttributeMaxDynamicSharedMemorySize, kp_smem);

    kp_project<<<PROJ_NODE_BLOCKS + PROJ_PATH_BLOCKS, 256, kp_smem>>>(etab_n, etab_p, Wt);
    // dummies: put k1b_cw at ncu's position-4 capture slot
    kdummy<<<1, 32>>>();
    kdummy<<<1, 32>>>();
    k1b_cw<<<BB * SS, 256>>>(x, Wt, bt, Wa, ba);
    k2_softmax<<<BB * LL, 128>>>();
    k3_codevec<<<BB * SS, 128>>>(x, etab_n, etab_p);
    k4_gates<<<BB * SS / 16, 512>>>(Wih, bih, bhh);
    k5_lstm<<<BB, 512>>>(Whh);
    {
        int total = BB * SS * NOUT;
        k6_fc<<<(total + 255) / 256, 256>>>(Wfc, bfc, out);
    }
}

// round 9
// speedup vs baseline: 1.9889x; 1.9889x over previous
#include <cuda_runtime.h>
#include <cuda_bf16.h>
#include <math.h>

// Problem dims
#define BB 16
#define SS 100
#define LL 100          // MAX_CODE_LEN
#define FEAT 20         // INPUT_DIM
#define EMB 100
#define DD 320          // D = 20 + 3*100
#define RNNIN 340       // 2*20 + 3*100
#define HID 128
#define G4 512
#define NOUT 10

#define NVOC_N 10002
#define NVOC_P 50002
#define PROJ_NODE_BLOCKS 79   // ceil(10002/128)
#define PROJ_PATH_BLOCKS 391  // ceil(50002/128)
#define WS_STRIDE 68          // multiple of 4: float4 stays 16B-aligned
#define AS_STRIDE 104         // multiple of 4

// -------- scratch (device globals; no allocation allowed) --------
static __device__ float g_Tn[NVOC_N * 640];    // [v][0:320]=start proj, [v][320:640]=end proj
static __device__ float g_Tp[NVOC_P * 320];    // path proj
static __device__ float g_cw[BB*LL*SS];        // [b][l][s]
static __device__ float g_aw[BB*SS*LL];        // [b][s][l]
static __device__ float g_rnn[BB*SS*RNNIN];    // [b][s][340]
static __device__ float g_gx[BB*SS*G4];        // x-part gates
static __device__ float g_hs[BB*SS*HID];       // lstm outputs
static __device__ float g_WihT[RNNIN*G4];      // [k][n] coalesced
static __device__ float4 g_Whh4[HID*HID];      // [k][n] -> gates (i,f,g,o) packed

__device__ __forceinline__ float sigf(float x) { return 1.0f / (1.0f + expf(-x)); }
__device__ __forceinline__ float tanh_fast(float x) {
    float y;
    asm("tanh.approx.f32 %0, %1;" : "=f"(y) : "f"(x));
    return y;
}

// ----------------------------------------------------------------
// K0: transpose W_ih; pack W_hh by gate quadruple
// ----------------------------------------------------------------
__global__ void k0_transpose(const float* __restrict__ Wih, const float* __restrict__ Whh) {
    int t = blockIdx.x * blockDim.x + threadIdx.x;
    if (t < RNNIN * G4) {          // Wih is [512][340]
        int n = t / RNNIN, k = t % RNNIN;
        g_WihT[k * G4 + n] = Wih[t];
    }
    if (t < HID * HID) {           // Whh is [512][128]: rows g*128+n, cols k
        int k = t / HID, n = t % HID;
        g_Whh4[k * HID + n] = make_float4(
            Whh[(0 * HID + n) * HID + k],
            Whh[(1 * HID + n) * HID + k],
            Whh[(2 * HID + n) * HID + k],
            Whh[(3 * HID + n) * HID + k]);
    }
}

// ----------------------------------------------------------------
// KP: project embedding tables through W_trans column blocks.
// ----------------------------------------------------------------
__global__ void __launch_bounds__(256, 1)
kp_project(const float* __restrict__ etab_n,
           const float* __restrict__ etab_p,
           const float* __restrict__ Wt)
{
    extern __shared__ float sm[];
    float* A_s = sm;                        // 128 * 104
    float* W_s = sm + 128 * AS_STRIDE;      // 100 * 68

    const int t = threadIdx.x;
    const bool isnode = blockIdx.x < PROJ_NODE_BLOCKS;
    const int vb = isnode ? blockIdx.x : blockIdx.x - PROJ_NODE_BLOCKS;
    const int v0 = vb * 128;
    const int nv = isnode ? NVOC_N : NVOC_P;
    const float* tab = isnode ? etab_n : etab_p;
    float* outp = isnode ? g_Tn : g_Tp;
    const int ostride = isnode ? 640 : 320;
    const int ndb = isnode ? 10 : 5;

    for (int e = t; e < 128 * EMB; e += 256) {
        int r = e / EMB, k = e % EMB;
        float v = 0.f;
        if (v0 + r < nv) v = tab[(v0 + r) * EMB + k];
        A_s[r * AS_STRIDE + k] = v;
    }

    const int tx = t & 15;
    const int ty = t >> 4;
    const int d0 = tx * 4;
    const int r0 = ty * 8;

    for (int db = 0; db < ndb; db++) {
        const int dbase = db * 64;
        int wrow, kofs;
        if (isnode) {
            if (db < 5) { wrow = dbase;       kofs = 0;   }
            else        { wrow = dbase - 320; kofs = 100; }
        } else          { wrow = dbase;       kofs = 200; }

        __syncthreads();
        for (int e = t; e < 64 * EMB; e += 256) {
            int d = e / EMB, k = e % EMB;
            W_s[k * WS_STRIDE + d] = Wt[(wrow + d) * DD + kofs + k];
        }
        __syncthreads();

        float acc[8][4];
#pragma unroll
        for (int i = 0; i < 8; i++)
#pragma unroll
            for (int j = 0; j < 4; j++) acc[i][j] = 0.f;

#pragma unroll 2
        for (int k = 0; k < EMB; k += 4) {
            float4 wv0 = *(const float4*)&W_s[(k + 0) * WS_STRIDE + d0];
            float4 wv1 = *(const float4*)&W_s[(k + 1) * WS_STRIDE + d0];
            float4 wv2 = *(const float4*)&W_s[(k + 2) * WS_STRIDE + d0];
            float4 wv3 = *(const float4*)&W_s[(k + 3) * WS_STRIDE + d0];
#pragma unroll
            for (int i = 0; i < 8; i++) {
                float4 a = *(const float4*)&A_s[(r0 + i) * AS_STRIDE + k];
                acc[i][0] += a.x * wv0.x + a.y * wv1.x + a.z * wv2.x + a.w * wv3.x;
                acc[i][1] += a.x * wv0.y + a.y * wv1.y + a.z * wv2.y + a.w * wv3.y;
                acc[i][2] += a.x * wv0.z + a.y * wv1.z + a.z * wv2.z + a.w * wv3.z;
                acc[i][3] += a.x * wv0.w + a.y * wv1.w + a.z * wv2.w + a.w * wv3.w;
            }
        }
#pragma unroll
        for (int i = 0; i < 8; i++) {
            int r = v0 + r0 + i;
            if (r < nv) {
                float4 o = make_float4(acc[i][0], acc[i][1], acc[i][2], acc[i][3]);
                *(float4*)&outp[r * ostride + dbase + d0] = o;
            }
        }
    }
}

// ----------------------------------------------------------------
// K1b: per (b,s): f_proj = feat @ Wt4^T + bt; per context l:
//   cw = ba + sum_d Wa[d]*tanh(Tn_s[si][d]+Tn_e[ei][d]+Tp[pi][d]+fproj[d])
// ----------------------------------------------------------------
__global__ void __launch_bounds__(256, 4)
k1b_cw(const float* __restrict__ x,
       const float* __restrict__ Wt,
       const float* __restrict__ bt,
       const float* __restrict__ Wa,
       const float* __restrict__ ba)
{
    __shared__ int si[LL], pi[LL], ei[LL];
    __shared__ float4 fproj4[DD/4], was4[DD/4];
    __shared__ float feat_s[FEAT];
    float* fproj = (float*)fproj4;
    float* was   = (float*)was4;

    const int bs = blockIdx.x;
    const int b = bs / SS, s = bs % SS;
    const int t = threadIdx.x;

    if (t < LL) {
        int xb = bs * DD + FEAT + 3 * t;
        si[t] = (int)x[xb];
        pi[t] = (int)x[xb + 1];
        ei[t] = (int)x[xb + 2];
    }
    if (t < FEAT) feat_s[t] = x[bs * DD + t];
    __syncthreads();

    for (int d = t; d < DD; d += 256) {
        float acc = bt[d];
        const float* wrow = &Wt[d * DD + 300];
#pragma unroll
        for (int k = 0; k < FEAT; k++) acc += feat_s[k] * wrow[k];
        fproj[d] = acc;
        was[d] = Wa[d];
    }
    __syncthreads();

    const int warp = t >> 5, lane = t & 31;
    const float bav = ba[0];
    for (int l = warp; l < LL; l += 8) {
        const float4* pn = (const float4*)&g_Tn[si[l] * 640];
        const float4* pe = (const float4*)&g_Tn[ei[l] * 640 + 320];
        const float4* pp = (const float4*)&g_Tp[pi[l] * 320];
        float sum = 0.f;
        for (int j = lane; j < DD/4; j += 32) {
            float4 a = pn[j], bb4 = pe[j], cc = pp[j], f = fproj4[j], w = was4[j];
            sum += w.x * tanh_fast(a.x + bb4.x + cc.x + f.x)
                 + w.y * tanh_fast(a.y + bb4.y + cc.y + f.y)
                 + w.z * tanh_fast(a.z + bb4.z + cc.z + f.z)
                 + w.w * tanh_fast(a.w + bb4.w + cc.w + f.w);
        }
#pragma unroll
        for (int off = 16; off; off >>= 1) sum += __shfl_xor_sync(~0u, sum, off);
        if (lane == 0)
            g_cw[(b * LL + l) * SS + s] = sum + bav;
    }
}

// ----------------------------------------------------------------
// K2: softmax over s (axis=1) for each (b,l); write aw in [b][s][l]
// ----------------------------------------------------------------
__global__ void k2_softmax() {
    const int bl = blockIdx.x;
    const int t  = threadIdx.x;    // 128
    const float* row = g_cw + bl * SS;
    float v0 = (t < SS) ? row[t] : -3.0e38f;

    __shared__ float sw[4];
    float v = v0;
#pragma unroll
    for (int off = 16; off; off >>= 1) v = fmaxf(v, __shfl_xor_sync(~0u, v, off));
    if ((t & 31) == 0) sw[t >> 5] = v;
    __syncthreads();
    float mx = fmaxf(fmaxf(sw[0], sw[1]), fmaxf(sw[2], sw[3]));
    __syncthreads();

    float e = (t < SS) ? expf(v0 - mx) : 0.f;
    float sv = e;
#pragma unroll
    for (int off = 16; off; off >>= 1) sv += __shfl_xor_sync(~0u, sv, off);
    if ((t & 31) == 0) sw[t >> 5] = sv;
    __syncthreads();
    float tot = sw[0] + sw[1] + sw[2] + sw[3];

    if (t < SS) {
        int b = bl / LL, l = bl % LL;
        g_aw[(b * SS + t) * LL + l] = e / tot;
    }
}

// ----------------------------------------------------------------
// K3: code_vec via re-gather; rnn_in = [feat(20), code_vec(320)]
// ----------------------------------------------------------------
__global__ void k3_codevec(const float* __restrict__ x,
                           const float* __restrict__ etab_n,
                           const float* __restrict__ etab_p)
{
    __shared__ float aw_s[LL];
    __shared__ int si[LL], pi[LL], ei[LL];
    __shared__ float awsum_s;
    const int bs = blockIdx.x;
    const int t  = threadIdx.x;   // 128

    if (t < LL) {
        aw_s[t] = g_aw[bs * LL + t];
        int xb = bs * DD + FEAT + 3 * t;
        si[t] = (int)x[xb];
        pi[t] = (int)x[xb + 1];
        ei[t] = (int)x[xb + 2];
    }
    __syncthreads();
    if (t == 0) {
        float a = 0.f;
        for (int l = 0; l < LL; l++) a += aw_s[l];
        awsum_s = a;
    }
    __syncthreads();

    float* outrow = g_rnn + bs * RNNIN;
    for (int j = t; j < RNNIN; j += 128) {
        float v;
        if (j < FEAT) {
            v = x[bs * DD + j];
        } else {
            int k = j - FEAT;
            float acc = 0.f;
            if (k < EMB) {
                for (int l = 0; l < LL; l++) acc += etab_n[si[l] * EMB + k] * aw_s[l];
            } else if (k < 2 * EMB) {
                int km = k - EMB;
                for (int l = 0; l < LL; l++) acc += etab_n[ei[l] * EMB + km] * aw_s[l];
            } else if (k < 3 * EMB) {
                int km = k - 2 * EMB;
                for (int l = 0; l < LL; l++) acc += etab_p[pi[l] * EMB + km] * aw_s[l];
            } else {
                acc = x[bs * DD + (k - 3 * EMB)] * awsum_s;
            }
            v = acc;
        }
        outrow[j] = v;
    }
}

// ----------------------------------------------------------------
// K4: g_gx = rnn_in @ W_ih^T + b_ih + b_hh  (coalesced WihT scalar loads)
// ----------------------------------------------------------------
__global__ void __launch_bounds__(512)
k4_gates(const float* __restrict__ bih, const float* __restrict__ bhh)
{
    __shared__ float A_s[16 * RNNIN];
    const int n  = threadIdx.x;
    const int r0 = blockIdx.x * 16;

    for (int e = n; e < 16 * RNNIN; e += 512)
        A_s[e] = g_rnn[r0 * RNNIN + e];
    __syncthreads();

    float acc[16];
#pragma unroll
    for (int i = 0; i < 16; i++) acc[i] = 0.f;

#pragma unroll 2
    for (int k = 0; k < RNNIN; k += 4) {
        float w0 = g_WihT[(k + 0) * G4 + n];
        float w1 = g_WihT[(k + 1) * G4 + n];
        float w2 = g_WihT[(k + 2) * G4 + n];
        float w3 = g_WihT[(k + 3) * G4 + n];
#pragma unroll
        for (int i = 0; i < 16; i++) {
            float4 a = *(const float4*)&A_s[i * RNNIN + k];
            acc[i] += a.x * w0 + a.y * w1 + a.z * w2 + a.w * w3;
        }
    }
    float bias = bih[n] + bhh[n];
#pragma unroll
    for (int i = 0; i < 16; i++)
        g_gx[(r0 + i) * G4 + n] = acc[i] + bias;
}

// ----------------------------------------------------------------
// K5: LSTM recurrence, gate-packed weights.
// 512 threads = 4 k-slices (q) x 128 hidden units (n).
// Thread (q,n) accumulates all 4 gates of unit n over k in [32q,32q+32)
// with coalesced LDG.128 of g_Whh4[k][n]; smem reduce over q; fused
// c/h update by threads n<128.
// ----------------------------------------------------------------
__global__ void __launch_bounds__(512)
k5_lstm()
{
    __shared__ float h_s[HID];
    __shared__ float4 red[4][HID];     // 8 KB
    const int b = blockIdx.x;
    const int n = threadIdx.x & 127;
    const int q = threadIdx.x >> 7;

    if (threadIdx.x < HID) h_s[threadIdx.x] = 0.f;
    float c = 0.f;
    __syncthreads();

    const float4* wbase = &g_Whh4[q * 32 * HID + n];
    const float*  hq    = &h_s[q * 32];

    for (int s = 0; s < SS; s++) {
        float4 acc = make_float4(0.f, 0.f, 0.f, 0.f);
#pragma unroll 8
        for (int kk = 0; kk < 32; kk++) {
            float4 w = wbase[kk * HID];
            float hk = hq[kk];
            acc.x += w.x * hk;
            acc.y += w.y * hk;
            acc.z += w.z * hk;
            acc.w += w.w * hk;
        }
        red[q][n] = acc;
        __syncthreads();
        if (threadIdx.x < HID) {
            float4 a0 = red[0][threadIdx.x];
            float4 a1 = red[1][threadIdx.x];
            float4 a2 = red[2][threadIdx.x];
            float4 a3 = red[3][threadIdx.x];
            const float* gx = &g_gx[(b * SS + s) * G4];
            float gi = a0.x + a1.x + a2.x + a3.x + gx[threadIdx.x];
            float gf = a0.y + a1.y + a2.y + a3.y + gx[HID + threadIdx.x];
            float gg = a0.z + a1.z + a2.z + a3.z + gx[2 * HID + threadIdx.x];
            float go = a0.w + a1.w + a2.w + a3.w + gx[3 * HID + threadIdx.x];
            c = sigf(gf) * c + sigf(gi) * tanhf(gg);
            float h = sigf(go) * tanhf(c);
            h_s[threadIdx.x] = h;
            g_hs[(b * SS + s) * HID + threadIdx.x] = h;
        }
        __syncthreads();
    }
}

// ----------------------------------------------------------------
// K6: out = sigmoid(hs @ W_fc^T + b_fc)
// ----------------------------------------------------------------
__global__ void k6_fc(const float* __restrict__ Wfc,
                      const float* __restrict__ bfc,
                      float* __restrict__ out)
{
    int t = blockIdx.x * blockDim.x + threadIdx.x;
    if (t >= BB * SS * NOUT) return;
    int bs = t / NOUT;
    int o  = t % NOUT;
    const float* hrow = g_hs + bs * HID;
    const float* wrow = Wfc + o * HID;
    float acc = bfc[o];
#pragma unroll 8
    for (int u = 0; u < HID; u++) acc += hrow[u] * wrow[u];
    out[t] = sigf(acc);
}

// ----------------------------------------------------------------
extern "C" void kernel_launch(void* const* d_in, const int* in_sizes, int n_in,
                              void* d_out, int out_size)
{
    const float* x      = (const float*)d_in[0];
    const float* etab_n = (const float*)d_in[1];
    const float* etab_p = (const float*)d_in[2];
    const float* Wt     = (const float*)d_in[3];
    const float* bt     = (const float*)d_in[4];
    const float* Wa     = (const float*)d_in[5];
    const float* ba     = (const float*)d_in[6];
    const float* Wih    = (const float*)d_in[7];
    const float* Whh    = (const float*)d_in[8];
    const float* bih    = (const float*)d_in[9];
    const float* bhh    = (const float*)d_in[10];
    const float* Wfc    = (const float*)d_in[11];
    const float* bfc    = (const float*)d_in[12];
    float* out = (float*)d_out;

    const int kp_smem = (128 * AS_STRIDE + 100 * WS_STRIDE) * 4;
    cudaFuncSetAttribute(kp_project, cudaFuncAttributeMaxDynamicSharedMemorySize, kp_smem);

    kp_project<<<PROJ_NODE_BLOCKS + PROJ_PATH_BLOCKS, 256, kp_smem>>>(etab_n, etab_p, Wt);
    k1b_cw<<<BB * SS, 256>>>(x, Wt, bt, Wa, ba);
    k2_softmax<<<BB * LL, 128>>>();
    k3_codevec<<<BB * SS, 128>>>(x, etab_n, etab_p);   // ncu 4th-launch slot
    {
        int total = RNNIN * G4;
        k0_transpose<<<(total + 255) / 256, 256>>>(Wih, Whh);
    }
    k4_gates<<<BB * SS / 16, 512>>>(bih, bhh);
    k5_lstm<<<BB, 512>>>();
    {
        int total = BB * SS * NOUT;
        k6_fc<<<(total + 255) / 256, 256>>>(Wfc, bfc, out);
    }
}